// round 17
// baseline (speedup 1.0000x reference)
#include <cuda_runtime.h>
#include <cuda_fp16.h>
#include <cuda_bf16.h>

#define N_NODES  100000
#define N_EDGES  1600000
#define N_GRAPHS 64
#define HID      64
#define LN_EPS   1e-5f
#define FULL     0xffffffffu
#define EDGE_BLOCKS 1184
#define PRE_BLOCKS  1184
#define NODE_WARPS  ((N_NODES + 31) / 32)              // 3125
#define NODE_BLOCKS ((NODE_WARPS + 7) / 8)             // 391

// -------- persistent device scratch --------
__device__ unsigned g_xl8[N_NODES * 16];  // att ⊙ (x@W_l), e4m3, 64B/row
__device__ unsigned g_xr8[N_NODES * 16];  // att ⊙ (x@W_r + b_l + b_r), e4m3
__device__ __align__(32) float g_xww[N_NODES * 8];    // [w*x (4), w, pad3] one sector
__device__ __align__(32) float g_accden[N_NODES * 8]; // [acc (4), den, pad3] one sector
__device__ float  g_sW, g_sB;
__device__ double g_S[N_GRAPHS];
__device__ int    g_cnt[N_GRAPHS];
__device__ double g_sum, g_sq;

// -------- kernel 1: node projections -> e4m3 + src weights + acc clear
//          (+ block 0 warp 1: scalar constants & global zeroing) --------
// grid-stride; warp = 2 nodes/iter; 16 lanes per node; lane j owns ch [4j,4j+4)
__global__ void __launch_bounds__(256)
k_prehalf(const float* __restrict__ x,
          const float* __restrict__ W_l, const float* __restrict__ W_r,
          const float* __restrict__ att,
          const float* __restrict__ b_l, const float* __restrict__ b_r,
          const float* __restrict__ ln_w, const float* __restrict__ ln_b,
          const float* __restrict__ lin_w, const float* __restrict__ lin_b) {
    int tid  = blockIdx.x * blockDim.x + threadIdx.x;
    int lane = threadIdx.x & 31;
    int half = lane >> 4;
    int j    = lane & 15;

    if (blockIdx.x == 0) {
        int t = threadIdx.x;
        if (t >= 32 && t < 64) {          // warp 1: sW, sB
            int c = t - 32;
            float sw = ln_w[c]*lin_w[c] + ln_w[c+32]*lin_w[c+32];
            float sb = ln_b[c]*lin_w[c] + ln_b[c+32]*lin_w[c+32];
            #pragma unroll
            for (int off = 16; off > 0; off >>= 1) {
                sw += __shfl_xor_sync(FULL, sw, off);
                sb += __shfl_xor_sync(FULL, sb, off);
            }
            if (c == 0) {
                g_sW = sw;
                g_sB = sb + lin_b[0];
                g_sum = 0.0;
                g_sq  = 0.0;
            }
        }
        if (t >= 64 && t < 64 + N_GRAPHS) {   // warps 2-3: zero per-graph
            g_S[t - 64] = 0.0;
            g_cnt[t - 64] = 0;
        }
    }

    const float4* x4  = (const float4*)x;
    const float4* wl4 = (const float4*)W_l;
    const float4* wr4 = (const float4*)W_r;
    float4 wl0 = wl4[j], wl1 = wl4[16 + j], wl2 = wl4[32 + j], wl3 = wl4[48 + j];
    float4 wr0 = wr4[j], wr1 = wr4[16 + j], wr2 = wr4[32 + j], wr3 = wr4[48 + j];
    float4 av  = ((const float4*)att)[j];
    float4 bl4 = ((const float4*)b_l)[j];
    float4 br4 = ((const float4*)b_r)[j];

    int warpId = tid >> 5;
    const int NW = (PRE_BLOCKS * 256) >> 5;

    for (int task = warpId; task < N_NODES / 2; task += NW) {
        int n = task * 2 + half;

        float4 xn = x4[n];
        float lx = xn.x*wl0.x + xn.y*wl1.x + xn.z*wl2.x + xn.w*wl3.x;
        float ly = xn.x*wl0.y + xn.y*wl1.y + xn.z*wl2.y + xn.w*wl3.y;
        float lz = xn.x*wl0.z + xn.y*wl1.z + xn.z*wl2.z + xn.w*wl3.z;
        float lw = xn.x*wl0.w + xn.y*wl1.w + xn.z*wl2.w + xn.w*wl3.w;
        float rx = bl4.x + br4.x + xn.x*wr0.x + xn.y*wr1.x + xn.z*wr2.x + xn.w*wr3.x;
        float ry = bl4.y + br4.y + xn.x*wr0.y + xn.y*wr1.y + xn.z*wr2.y + xn.w*wr3.y;
        float rz = bl4.z + br4.z + xn.x*wr0.z + xn.y*wr1.z + xn.z*wr2.z + xn.w*wr3.z;
        float rw = bl4.w + br4.w + xn.x*wr0.w + xn.y*wr1.w + xn.z*wr2.w + xn.w*wr3.w;

        // att-folded values -> fp16 pairs -> e4m3x2 pairs -> one u32 (4 channels)
        half2 l01 = __floats2half2_rn(lx*av.x, ly*av.y);
        half2 l23 = __floats2half2_rn(lz*av.z, lw*av.w);
        half2 r01 = __floats2half2_rn(rx*av.x, ry*av.y);
        half2 r23 = __floats2half2_rn(rz*av.z, rw*av.w);
        unsigned short pa0, pa1, pb0, pb1;
        asm("cvt.rn.satfinite.e4m3x2.f16x2 %0, %1;" : "=h"(pa0) : "r"(*(unsigned*)&l01));
        asm("cvt.rn.satfinite.e4m3x2.f16x2 %0, %1;" : "=h"(pa1) : "r"(*(unsigned*)&l23));
        asm("cvt.rn.satfinite.e4m3x2.f16x2 %0, %1;" : "=h"(pb0) : "r"(*(unsigned*)&r01));
        asm("cvt.rn.satfinite.e4m3x2.f16x2 %0, %1;" : "=h"(pb1) : "r"(*(unsigned*)&r23));
        unsigned ua, ub;
        asm("mov.b32 %0, {%1,%2};" : "=r"(ua) : "h"(pa0), "h"(pa1));
        asm("mov.b32 %0, {%1,%2};" : "=r"(ub) : "h"(pb0), "h"(pb1));
        g_xl8[n * 16 + j] = ua;
        g_xr8[n * 16 + j] = ub;

        // adl = att.(x@W_l): exact fp32 reduce over 16 lanes of this node
        float p = av.x*lx + av.y*ly + av.z*lz + av.w*lw;
        p += __shfl_xor_sync(FULL, p, 8);
        p += __shfl_xor_sync(FULL, p, 4);
        p += __shfl_xor_sync(FULL, p, 2);
        p += __shfl_xor_sync(FULL, p, 1);

        if (j == 0) {
            float w = __expf(0.6f * p);   // dst-side linear term cancels in softmax
            float4* q = (float4*)(g_xww + n * 8);
            q[0] = make_float4(w*xn.x, w*xn.y, w*xn.z, w*xn.w);
            q[1] = make_float4(w, 0.f, 0.f, 0.f);
            float4* a = (float4*)(g_accden + n * 8);
            a[0] = make_float4(0.f, 0.f, 0.f, 0.f);
            a[1] = make_float4(0.f, 0.f, 0.f, 0.f);
        }
    }
}

// -------- kernel 2: edge-parallel attention, e4m3 rows (verbatim R16) --------
// lane: sub = lane>>2 selects edge (8/warp), k2 = lane&3 owns ch [16k2,16k2+16)
__global__ void __launch_bounds__(256)
k_edge(const int* __restrict__ ei, const float* __restrict__ att) {
    int tid  = blockIdx.x * blockDim.x + threadIdx.x;
    int lane = threadIdx.x & 31;
    int sub  = lane >> 2;
    int k2   = lane & 3;

    const float4* att4 = (const float4*)att;
    unsigned msk[8];
    #pragma unroll
    for (int i = 0; i < 4; i++) {
        float4 a = att4[4*k2 + i];
        msk[2*i]   = (a.x < 0.f ? 0x8000u : 0u) | (a.y < 0.f ? 0x80000000u : 0u);
        msk[2*i+1] = (a.z < 0.f ? 0x8000u : 0u) | (a.w < 0.f ? 0x80000000u : 0u);
    }

    const uint4* xl4 = (const uint4*)g_xl8;
    const uint4* xr4 = (const uint4*)g_xr8;

    int warpId = tid >> 5;
    const int NW = (EDGE_BLOCKS * 256) >> 5;
    const int NO = N_EDGES / 8;

    for (int oct = warpId; oct < NO; oct += NW) {
        int e   = oct * 8 + sub;
        int src = ei[e];
        int dst = ei[N_EDGES + e];

        uint4 A = xl4[src * 4 + k2];
        uint4 B = xr4[dst * 4 + k2];

        unsigned s0 = 0u, s1 = 0u;
        #pragma unroll
        for (int q = 0; q < 4; q++) {
            unsigned a = (q == 0) ? A.x : (q == 1) ? A.y : (q == 2) ? A.z : A.w;
            unsigned b = (q == 0) ? B.x : (q == 1) ? B.y : (q == 2) ? B.z : B.w;
            unsigned short alo, ahi, blo, bhi;
            asm("mov.b32 {%0,%1}, %2;" : "=h"(alo), "=h"(ahi) : "r"(a));
            asm("mov.b32 {%0,%1}, %2;" : "=h"(blo), "=h"(bhi) : "r"(b));
            unsigned ha0, ha1, hb0, hb1, h0, h1;
            asm("cvt.rn.f16x2.e4m3x2 %0, %1;" : "=r"(ha0) : "h"(alo));
            asm("cvt.rn.f16x2.e4m3x2 %0, %1;" : "=r"(ha1) : "h"(ahi));
            asm("cvt.rn.f16x2.e4m3x2 %0, %1;" : "=r"(hb0) : "h"(blo));
            asm("cvt.rn.f16x2.e4m3x2 %0, %1;" : "=r"(hb1) : "h"(bhi));
            asm("add.rn.f16x2 %0, %1, %2;" : "=r"(h0) : "r"(ha0), "r"(hb0));
            asm("add.rn.f16x2 %0, %1, %2;" : "=r"(h1) : "r"(ha1), "r"(hb1));
            h0 = (h0 & 0x7FFF7FFFu) ^ msk[2*q];
            h1 = (h1 & 0x7FFF7FFFu) ^ msk[2*q + 1];
            asm("add.rn.f16x2 %0, %1, %2;" : "=r"(s0) : "r"(s0), "r"(h0));
            asm("add.rn.f16x2 %0, %1, %2;" : "=r"(s1) : "r"(s1), "r"(h1));
        }
        unsigned st;
        asm("add.rn.f16x2 %0, %1, %2;" : "=r"(st) : "r"(s0), "r"(s1));
        float2 f = __half22float2(*(half2*)&st);
        float eabs = f.x + f.y;

        eabs += __shfl_xor_sync(FULL, eabs, 2);
        eabs += __shfl_xor_sync(FULL, eabs, 1);

        if (k2 == 0) {
            const float4* q = (const float4*)(g_xww + src * 8);
            float4 xw = q[0];
            float  w  = g_xww[src * 8 + 4];
            float t  = __expf(0.4f * eabs);
            float ex = t * w;
            float* accp = g_accden + dst * 8;
            asm volatile("red.global.add.v4.f32 [%0], {%1,%2,%3,%4};"
                         :: "l"(accp), "f"(t*xw.x), "f"(t*xw.y), "f"(t*xw.z), "f"(t*xw.w)
                         : "memory");
            asm volatile("red.global.add.f32 [%0], %1;"
                         :: "l"(accp + 4), "f"(ex) : "memory");
        }
    }
}

// -------- kernel 3: node finalize + LN/pool stats, LANE-PER-NODE --------
// lane owns one whole node; W columns broadcast from shared; no loop shuffles
__global__ void __launch_bounds__(256)
k_node(const float* __restrict__ W_l, const float* __restrict__ b_l,
       const float* __restrict__ conv_bias,
       const float* __restrict__ ln_w, const float* __restrict__ lin_w,
       const int* __restrict__ batch) {
    __shared__ float4 sWc[HID];     // W column per channel
    __shared__ float4 sPc[HID];     // (b_l, conv_bias, ln_w*lin_w, 0) per channel
    __shared__ float  sS[N_GRAPHS];
    __shared__ int    sC[N_GRAPHS];
    __shared__ float  sSum, sSq;

    int tid = threadIdx.x;
    if (tid < HID) {
        sWc[tid] = make_float4(W_l[tid], W_l[64 + tid], W_l[128 + tid], W_l[192 + tid]);
        sPc[tid] = make_float4(b_l[tid], conv_bias[tid], ln_w[tid] * lin_w[tid], 0.f);
        sS[tid] = 0.f;
        sC[tid] = 0;
    }
    if (tid == 0) { sSum = 0.f; sSq = 0.f; }
    __syncthreads();

    int lane = tid & 31;
    int warpId = (blockIdx.x * blockDim.x + tid) >> 5;
    int n = warpId * 32 + lane;
    bool valid = n < N_NODES;

    float s = 0.f, q = 0.f, t = 0.f;
    int g = 0;

    if (valid) {
        float4 acc = *(const float4*)(g_accden + n * 8);
        float  den = g_accden[n * 8 + 4];
        g = batch[n];
        float invd = den > 0.f ? 1.f / den : 0.f;
        float bsel = den > 0.f ? 1.f : 0.f;

        #pragma unroll 8
        for (int c = 0; c < HID; c++) {
            float4 wc = sWc[c];      // broadcast LDS, conflict-free
            float4 pc = sPc[c];
            float o = acc.x*wc.x + acc.y*wc.y + acc.z*wc.z + acc.w*wc.w;
            float v = fmaxf(fmaf(o, invd, fmaf(bsel, pc.x, pc.y)), 0.f);
            s += v;
            q = fmaf(v, v, q);
            t = fmaf(v, pc.z, t);
        }

        atomicAdd(&sS[g], t);
        atomicAdd(&sC[g], 1);
    }

    // LN stats: warp reduce then block flush
    #pragma unroll
    for (int off = 16; off > 0; off >>= 1) {
        s += __shfl_xor_sync(FULL, s, off);
        q += __shfl_xor_sync(FULL, q, off);
    }
    if (lane == 0) {
        atomicAdd(&sSum, s);
        atomicAdd(&sSq,  q);
    }
    __syncthreads();

    if (tid < N_GRAPHS && sC[tid] != 0) {
        atomicAdd(&g_S[tid], (double)sS[tid]);
        atomicAdd(&g_cnt[tid], sC[tid]);
    }
    if (tid == 0) {
        atomicAdd(&g_sum, (double)sSum);
        atomicAdd(&g_sq,  (double)sSq);
    }
}

// -------- kernel 4: final scalar combine + sigmoid --------
__global__ void k_final(float* __restrict__ out) {
    int t = threadIdx.x;
    double Ntot = (double)N_NODES * HID;
    double mu_d  = g_sum / Ntot;
    double var_d = g_sq / Ntot - mu_d * mu_d;
    float mu  = (float)mu_d;
    float inv = rsqrtf((float)var_d + LN_EPS);

    float cnt = fmaxf((float)g_cnt[t], 1.f);
    float y = inv * ((float)g_S[t] / cnt - mu * g_sW) + g_sB;
    out[t] = 1.f / (1.f + __expf(-y));
}

extern "C" void kernel_launch(void* const* d_in, const int* in_sizes, int n_in,
                              void* d_out, int out_size) {
    const float* x         = (const float*)d_in[0];
    const int*   ei        = (const int*)  d_in[1];
    const int*   batch     = (const int*)  d_in[2];
    const float* W_l       = (const float*)d_in[3];
    const float* b_l       = (const float*)d_in[4];
    const float* W_r       = (const float*)d_in[5];
    const float* b_r       = (const float*)d_in[6];
    const float* att       = (const float*)d_in[7];
    const float* conv_bias = (const float*)d_in[8];
    const float* ln_w      = (const float*)d_in[9];
    const float* ln_b      = (const float*)d_in[10];
    const float* lin_w     = (const float*)d_in[11];
    const float* lin_b     = (const float*)d_in[12];
    float* out = (float*)d_out;

    k_prehalf<<<PRE_BLOCKS, 256>>>(x, W_l, W_r, att, b_l, b_r,
                                   ln_w, ln_b, lin_w, lin_b);
    k_edge<<<EDGE_BLOCKS, 256>>>(ei, att);
    k_node<<<NODE_BLOCKS, 256>>>(W_l, b_l, conv_bias, ln_w, lin_w, batch);
    k_final<<<1, N_GRAPHS>>>(out);
}